// round 16
// baseline (speedup 1.0000x reference)
#include <cuda_runtime.h>
#include <cstdint>
#include <math.h>

#define TPB 256
#define WARPS (TPB / 32)              // 8
#define CH 30
#define CELLS_W 32                    // cells per warp-tile
#define TILE_FLOATS (CELLS_W * CH)    // 960 floats per array per tile
#define TILE_F4 (TILE_FLOATS / 4)     // 240
#define TILE_BYTES (TILE_FLOATS * 4)  // 3840
#define WSLOT_FLOATS (4 * TILE_FLOATS)  // 2 stages x 2 arrays
#define MAXG 2048

__device__ float g_partials[MAXG];
__device__ int   g_count;             // zero-init; reset by last block each launch

__device__ __forceinline__ unsigned su32(const void* p) {
    return (unsigned)__cvta_generic_to_shared(p);
}
__device__ __forceinline__ void cp16(unsigned s, const void* g) {
    asm volatile("cp.async.cg.shared.global [%0], [%1], 16;" :: "r"(s), "l"(g));
}

__device__ __forceinline__ float warp_sum(float v) {
#pragma unroll
    for (int off = 16; off > 0; off >>= 1)
        v += __shfl_down_sync(0xFFFFFFFFu, v, off);
    return v;
}

// Per-cell YOLO loss; works on shared or global pointers (generic loads).
// IoU is translation-invariant: grid offsets cancel.
__device__ __forceinline__ float cell_loss(const float* pp, const float* tt)
{
    float p[CH], t[CH];
    const float2* p2 = reinterpret_cast<const float2*>(pp);
    const float2* t2 = reinterpret_cast<const float2*>(tt);
#pragma unroll
    for (int j = 0; j < 15; j++) {
        float2 a = p2[j];  p[2*j] = a.x;  p[2*j+1] = a.y;
        float2 b = t2[j];  t[2*j] = b.x;  t[2*j+1] = b.y;
    }

    const float ratio = 1.0f / 7.0f;
    const float tconf = t[4];

    if (!(tconf > 0.0f)) {
        float c1 = p[4], c2 = p[9];
        return 0.5f * (c1 * c1 + c2 * c2);
    }

    float tcx = t[0] * ratio, tcy = t[1] * ratio;
    float tw = t[2], th = t[3];
    float tx1 = tcx - tw * 0.5f, ty1 = tcy - th * 0.5f;
    float tx2 = tcx + tw * 0.5f, ty2 = tcy + th * 0.5f;
    float areaT = (tx2 - tx1) * (ty2 - ty1);

    auto iou_with = [&](const float* b) -> float {
        float bcx = b[0] * ratio, bcy = b[1] * ratio;
        float bw = b[2], bh = b[3];
        float x1 = bcx - bw * 0.5f, y1 = bcy - bh * 0.5f;
        float x2 = bcx + bw * 0.5f, y2 = bcy + bh * 0.5f;
        float iw = fmaxf(fminf(x2, tx2) - fmaxf(x1, tx1), 0.0f);
        float ih = fmaxf(fminf(y2, ty2) - fmaxf(y1, ty1), 0.0f);
        float inter = iw * ih;
        float area = (x2 - x1) * (y2 - y1);
        return inter / (area + areaT - inter);
    };

    float iou1 = iou_with(p);
    float iou2 = iou_with(p + 5);
    bool resp = iou1 > iou2;
    float pcx = resp ? p[0] : p[5];
    float pcy = resp ? p[1] : p[6];
    float pcw = resp ? p[2] : p[7];
    float pch = resp ? p[3] : p[8];
    float pcc = resp ? p[4] : p[9];
    float iouS = resp ? iou1 : iou2;

    float dx = pcx - t[0];
    float dy = pcy - t[1];
    float sw = sqrtf(fmaxf(pcw, 1e-6f)) - sqrtf(fmaxf(t[2], 1e-6f));
    float sh = sqrtf(fmaxf(pch, 1e-6f)) - sqrtf(fmaxf(t[3], 1e-6f));
    float coord = 5.0f * (dx*dx + dy*dy + sw*sw + sh*sh);

    float dc = pcc - iouS;
    float conf = dc * dc;

    float cls = 0.0f;
#pragma unroll
    for (int k = 10; k < 30; k++) {
        float d = p[k] - t[k];
        cls += d * d;
    }
    return coord + conf + cls;
}

// Block reduction valid for any TPB multiple of 32.
__device__ __forceinline__ float block_sum(float v, float* wred, int tid) {
    const int lane = tid & 31;
    const int w    = tid >> 5;
    float s = warp_sum(v);
    if (lane == 0) wred[w] = s;
    __syncthreads();
    float r = 0.0f;
    if (w == 0) {
        float x = (lane < WARPS) ? wred[lane] : 0.0f;
        r = warp_sum(x);
    }
    return r;   // valid in warp 0 lane 0
}

// R13's warp-autonomous double-buffered streaming kernel (TPB=256, 8 warps),
// with ONLY the tail fused (last-block-done, fixed-order -> deterministic).
__global__ void __launch_bounds__(TPB)
yolo_warp_fused(const float* __restrict__ predicts,
                const float* __restrict__ targets,
                int n_cells, int ntiles, float* __restrict__ out)
{
    extern __shared__ float dsm[];
    __shared__ float wred[WARPS];
    __shared__ bool  is_last;

    const int tid  = threadIdx.x;
    const int lane = tid & 31;
    const int w    = tid >> 5;
    const int gw     = blockIdx.x * WARPS + w;     // global warp id
    const int nwarps = gridDim.x * WARPS;

    float*   wbase   = dsm + w * WSLOT_FLOATS;     // 15360B per warp
    unsigned wbase_s = su32(wbase);

    const int nt_w = (ntiles > gw) ? ((ntiles - gw - 1) / nwarps + 1) : 0;

    auto issue = [&](int m) {
        const int tile = gw + m * nwarps;
        const int s = m & 1;
        unsigned pd = wbase_s + s * (2 * TILE_BYTES);
        unsigned td = pd + TILE_BYTES;
        const float4* pg = reinterpret_cast<const float4*>(predicts + (long long)tile * TILE_FLOATS);
        const float4* tg = reinterpret_cast<const float4*>(targets  + (long long)tile * TILE_FLOATS);
#pragma unroll
        for (int i = 0; i < 8; i++) {
            int idx = i * 32 + lane;
            if (idx < TILE_F4) {
                cp16(pd + idx * 16, pg + idx);
                cp16(td + idx * 16, tg + idx);
            }
        }
        asm volatile("cp.async.commit_group;");
    };

    float acc = 0.0f;

    // remainder cells beyond full tiles (none for this shape; guard)
    if (gw == 0) {
        for (int c = ntiles * CELLS_W + lane; c < n_cells; c += 32)
            acc += cell_loss(predicts + (long long)c * CH,
                             targets  + (long long)c * CH);
    }

    if (nt_w > 0) issue(0);

    for (int m = 0; m < nt_w; m++) {
        const bool hn = (m + 1) < nt_w;
        if (hn) issue(m + 1);
        if (hn) asm volatile("cp.async.wait_group 1;");
        else    asm volatile("cp.async.wait_group 0;");
        __syncwarp();                               // tile m visible warp-wide

        const float* sp = wbase + (m & 1) * (2 * TILE_FLOATS) + lane * CH;
        acc += cell_loss(sp, sp + TILE_FLOATS);

        __syncwarp();                               // all lanes done before buffer reuse
    }

    // Block reduction, then fused deterministic finish.
    float bsum = block_sum(acc, wred, tid);
    if (tid == 0) {
        g_partials[blockIdx.x] = bsum;
        __threadfence();
        int old = atomicAdd(&g_count, 1);
        is_last = (old == gridDim.x - 1);
    }
    __syncthreads();

    if (is_last) {
        const int nb = gridDim.x;
        float v = 0.0f;
        for (int i = tid; i < nb; i += TPB)         // fixed order -> deterministic
            v += g_partials[i];
        float total = block_sum(v, wred, tid);
        if (tid == 0) {
            out[0] = total;
            g_count = 0;                            // reset for next graph replay
        }
    }
}

extern "C" void kernel_launch(void* const* d_in, const int* in_sizes, int n_in,
                              void* d_out, int out_size)
{
    const float* predicts = (const float*)d_in[0];
    const float* targets  = (const float*)d_in[1];
    float* out = (float*)d_out;

    int n_cells = in_sizes[0] / CH;            // 401408
    int ntiles  = n_cells / CELLS_W;           // 12544 full warp-tiles (exact)

    int blocks = 148;                          // 1 per SM, persistent warps
    if (blocks > MAXG) blocks = MAXG;

    const int smem_bytes = WARPS * WSLOT_FLOATS * sizeof(float);  // 122880
    cudaFuncSetAttribute(yolo_warp_fused,
                         cudaFuncAttributeMaxDynamicSharedMemorySize, smem_bytes);

    yolo_warp_fused<<<blocks, TPB, smem_bytes>>>(predicts, targets,
                                                 n_cells, ntiles, out);
}

// round 17
// speedup vs baseline: 1.5259x; 1.5259x over previous
#include <cuda_runtime.h>
#include <cstdint>
#include <math.h>

#define TPB 256
#define WARPS (TPB / 32)
#define CH 30
#define CELLS_W 32                    // cells per warp-tile
#define TILE_FLOATS (CELLS_W * CH)    // 960 floats per array per tile
#define TILE_F4 (TILE_FLOATS / 4)     // 240
#define TILE_BYTES (TILE_FLOATS * 4)  // 3840
#define WSLOT_FLOATS (4 * TILE_FLOATS)  // 2 stages x 2 arrays = 3840 floats
#define MAXG 2048

__device__ float g_partials[MAXG];

__device__ __forceinline__ unsigned su32(const void* p) {
    return (unsigned)__cvta_generic_to_shared(p);
}
__device__ __forceinline__ void cp16(unsigned s, const void* g) {
    asm volatile("cp.async.cg.shared.global [%0], [%1], 16;" :: "r"(s), "l"(g));
}

// Per-cell YOLO loss; works on shared or global pointers (generic loads).
// IoU is translation-invariant: grid offsets cancel.
__device__ __forceinline__ float cell_loss(const float* pp, const float* tt)
{
    float p[CH], t[CH];
    const float2* p2 = reinterpret_cast<const float2*>(pp);
    const float2* t2 = reinterpret_cast<const float2*>(tt);
#pragma unroll
    for (int j = 0; j < 15; j++) {
        float2 a = p2[j];  p[2*j] = a.x;  p[2*j+1] = a.y;
        float2 b = t2[j];  t[2*j] = b.x;  t[2*j+1] = b.y;
    }

    const float ratio = 1.0f / 7.0f;
    const float tconf = t[4];

    if (!(tconf > 0.0f)) {
        float c1 = p[4], c2 = p[9];
        return 0.5f * (c1 * c1 + c2 * c2);
    }

    float tcx = t[0] * ratio, tcy = t[1] * ratio;
    float tw = t[2], th = t[3];
    float tx1 = tcx - tw * 0.5f, ty1 = tcy - th * 0.5f;
    float tx2 = tcx + tw * 0.5f, ty2 = tcy + th * 0.5f;
    float areaT = (tx2 - tx1) * (ty2 - ty1);

    auto iou_with = [&](const float* b) -> float {
        float bcx = b[0] * ratio, bcy = b[1] * ratio;
        float bw = b[2], bh = b[3];
        float x1 = bcx - bw * 0.5f, y1 = bcy - bh * 0.5f;
        float x2 = bcx + bw * 0.5f, y2 = bcy + bh * 0.5f;
        float iw = fmaxf(fminf(x2, tx2) - fmaxf(x1, tx1), 0.0f);
        float ih = fmaxf(fminf(y2, ty2) - fmaxf(y1, ty1), 0.0f);
        float inter = iw * ih;
        float area = (x2 - x1) * (y2 - y1);
        return inter / (area + areaT - inter);
    };

    float iou1 = iou_with(p);
    float iou2 = iou_with(p + 5);
    bool resp = iou1 > iou2;
    float pcx = resp ? p[0] : p[5];
    float pcy = resp ? p[1] : p[6];
    float pcw = resp ? p[2] : p[7];
    float pch = resp ? p[3] : p[8];
    float pcc = resp ? p[4] : p[9];
    float iouS = resp ? iou1 : iou2;

    float dx = pcx - t[0];
    float dy = pcy - t[1];
    float sw = sqrtf(fmaxf(pcw, 1e-6f)) - sqrtf(fmaxf(t[2], 1e-6f));
    float sh = sqrtf(fmaxf(pch, 1e-6f)) - sqrtf(fmaxf(t[3], 1e-6f));
    float coord = 5.0f * (dx*dx + dy*dy + sw*sw + sh*sh);

    float dc = pcc - iouS;
    float conf = dc * dc;

    float cls = 0.0f;
#pragma unroll
    for (int k = 10; k < 30; k++) {
        float d = p[k] - t[k];
        cls += d * d;
    }
    return coord + conf + cls;
}

// Warp-autonomous double-buffered streaming kernel: NO block barriers in the
// hot loop. Each warp pipelines its own 32-cell tiles through its private
// smem slice with cp.async, so warps drift out of phase and the SM issues
// memory requests continuously.
__global__ void __launch_bounds__(TPB)
yolo_warp_main(const float* __restrict__ predicts,
               const float* __restrict__ targets,
               int n_cells, int ntiles)
{
    extern __shared__ float dsm[];
    __shared__ float red[TPB];

    const int tid  = threadIdx.x;
    const int lane = tid & 31;
    const int w    = tid >> 5;
    const int gw     = blockIdx.x * WARPS + w;     // global warp id
    const int nwarps = gridDim.x * WARPS;

    float*   wbase   = dsm + w * WSLOT_FLOATS;     // 15360B per warp
    unsigned wbase_s = su32(wbase);

    const int nt_w = (ntiles > gw) ? ((ntiles - gw - 1) / nwarps + 1) : 0;

    auto issue = [&](int m) {
        const int tile = gw + m * nwarps;
        const int s = m & 1;
        unsigned pd = wbase_s + s * (2 * TILE_BYTES);
        unsigned td = pd + TILE_BYTES;
        const float4* pg = reinterpret_cast<const float4*>(predicts + (long long)tile * TILE_FLOATS);
        const float4* tg = reinterpret_cast<const float4*>(targets  + (long long)tile * TILE_FLOATS);
#pragma unroll
        for (int i = 0; i < 8; i++) {
            int idx = i * 32 + lane;
            if (idx < TILE_F4) {
                cp16(pd + idx * 16, pg + idx);
                cp16(td + idx * 16, tg + idx);
            }
        }
        asm volatile("cp.async.commit_group;");
    };

    float acc = 0.0f;

    // remainder cells beyond full tiles (none for this shape; guard)
    if (gw == 0) {
        for (int c = ntiles * CELLS_W + lane; c < n_cells; c += 32)
            acc += cell_loss(predicts + (long long)c * CH,
                             targets  + (long long)c * CH);
    }

    if (nt_w > 0) issue(0);

    for (int m = 0; m < nt_w; m++) {
        const bool hn = (m + 1) < nt_w;
        if (hn) issue(m + 1);
        if (hn) asm volatile("cp.async.wait_group 1;");
        else    asm volatile("cp.async.wait_group 0;");
        __syncwarp();                               // tile m visible warp-wide

        const float* sp = wbase + (m & 1) * (2 * TILE_FLOATS) + lane * CH;
        acc += cell_loss(sp, sp + TILE_FLOATS);

        __syncwarp();                               // all lanes done before buffer reuse
    }

    // Block tree reduction (once per block).
    red[tid] = acc;
    __syncthreads();
#pragma unroll
    for (int s = TPB / 2; s >= 32; s >>= 1) {
        if (tid < s) red[tid] += red[tid + s];
        __syncthreads();
    }
    if (tid < 32) {
        float v = red[tid];
#pragma unroll
        for (int off = 16; off > 0; off >>= 1)
            v += __shfl_down_sync(0xFFFFFFFFu, v, off);
        if (tid == 0) g_partials[blockIdx.x] = v;
    }
}

__global__ void __launch_bounds__(256)
yolo_loss_final(int n_partials, float* __restrict__ out)
{
    __shared__ float red[256];
    const int tid = threadIdx.x;
    float v = 0.0f;
    for (int i = tid; i < n_partials; i += 256)    // fixed order -> deterministic
        v += g_partials[i];
    red[tid] = v;
    __syncthreads();
#pragma unroll
    for (int s = 128; s >= 32; s >>= 1) {
        if (tid < s) red[tid] += red[tid + s];
        __syncthreads();
    }
    if (tid < 32) {
        float w = red[tid];
#pragma unroll
        for (int off = 16; off > 0; off >>= 1)
            w += __shfl_down_sync(0xFFFFFFFFu, w, off);
        if (tid == 0) out[0] = w;
    }
}

extern "C" void kernel_launch(void* const* d_in, const int* in_sizes, int n_in,
                              void* d_out, int out_size)
{
    const float* predicts = (const float*)d_in[0];
    const float* targets  = (const float*)d_in[1];
    float* out = (float*)d_out;

    int n_cells = in_sizes[0] / CH;            // 401408
    int ntiles  = n_cells / CELLS_W;           // 12544 full warp-tiles (exact)

    int blocks = 148;                          // 1 per SM, persistent warps
    if (blocks > MAXG) blocks = MAXG;

    const int smem_bytes = WARPS * WSLOT_FLOATS * sizeof(float);  // 122880
    cudaFuncSetAttribute(yolo_warp_main,
                         cudaFuncAttributeMaxDynamicSharedMemorySize, smem_bytes);

    yolo_warp_main<<<blocks, TPB, smem_bytes>>>(predicts, targets, n_cells, ntiles);
    yolo_loss_final<<<1, 256>>>(blocks, out);
}